// round 12
// baseline (speedup 1.0000x reference)
#include <cuda_runtime.h>
#include <cuda_bf16.h>
#include <cstdint>
#include <math.h>

#define NN 12800
#define GG 128
#define EB 51200
#define EC 204800
#define AGGN (NN*1024)

__device__ __forceinline__ uint32_t smem_to_u32(const void* p) {
    uint32_t a;
    asm("{ .reg .u64 t; cvta.to.shared.u64 t, %1; cvt.u32.u64 %0, t; }" : "=r"(a) : "l"(p));
    return a;
}
#define LDSM_X4(r0,r1,r2,r3, addr) \
    asm volatile("ldmatrix.sync.aligned.m8n8.x4.shared.b16 {%0,%1,%2,%3}, [%4];" \
        : "=r"(r0),"=r"(r1),"=r"(r2),"=r"(r3) : "r"(addr))
#define LDSM_X4_T(r0,r1,r2,r3, addr) \
    asm volatile("ldmatrix.sync.aligned.m8n8.x4.trans.shared.b16 {%0,%1,%2,%3}, [%4];" \
        : "=r"(r0),"=r"(r1),"=r"(r2),"=r"(r3) : "r"(addr))
#define MMA_BF16(d, a0,a1,a2,a3, b0,b1) \
    asm volatile("mma.sync.aligned.m16n8k16.row.col.f32.bf16.bf16.f32 " \
        "{%0,%1,%2,%3}, {%4,%5,%6,%7}, {%8,%9}, {%0,%1,%2,%3};" \
        : "+f"((d)[0]),"+f"((d)[1]),"+f"((d)[2]),"+f"((d)[3]) \
        : "r"(a0),"r"(a1),"r"(a2),"r"(a3), "r"(b0),"r"(b1))
#define CPA16(dst, src) \
    asm volatile("cp.async.cg.shared.global [%0], [%1], 16;" :: "r"(dst), "l"(src))
#define CPC() asm volatile("cp.async.commit_group;" ::: "memory")

// ---------------- scratch (no allocations allowed) ----------------
__device__ float g_hA[NN*128];     // final node output fp32 (readout input)
__device__ float g_X[NN*512];      // [A1 | A2+b1 | B1 | B2+preb] per node
__device__ float g_C5[5*EB*128];   // ef @ P3, all 5 layers (computed upfront)
__device__ float g_bx[5*512];
__device__ __align__(16) unsigned char g_Bimg[5*65536];       // W2 bf16 hi+lo per layer (comp)
__device__ __align__(16) __nv_bfloat16 g_WxI[2*5*65536];
__device__ __align__(16) __nv_bfloat16 g_P3I[2*5*16384];
__device__ __align__(16) __nv_bfloat16 g_WeI[2*5*147456];
__device__ __align__(16) __nv_bfloat16 g_OnI[4*16384];        // hiW1 | loW1 | hiW2 | loW2
__device__ __align__(16) __nv_bfloat16 g_hImgA[2*NN*128];
__device__ __align__(16) __nv_bfloat16 g_hImgB[2*NN*128];
__device__ __align__(16) __nv_bfloat16 g_efI[2*EB*128];
__device__ __align__(16) __nv_bfloat16 g_aggI[2*NN*1024];     // hi then lo
__device__ __align__(16) __nv_bfloat16 g_t1I[2*NN*128];

__device__ __forceinline__ void split_bf(float v, __nv_bfloat16& h, __nv_bfloat16& l) {
    h = __float2bfloat16(v);
    l = __float2bfloat16(v - __bfloat162float(h));
}

// ---------------- ONE merged weight-pack kernel (all images) ----------------
__global__ void pack_all_kernel(
    const float* __restrict__ pcW1, const float* __restrict__ preW,
    const float* __restrict__ pcB1, const float* __restrict__ preB,
    const float* __restrict__ postW, const float* __restrict__ pcW2,
    const float* __restrict__ onW1, const float* __restrict__ onW2)
{
    long idx = (long)blockIdx.x * 256 + threadIdx.x;
    if (idx < 327680) {
        int l = idx >> 16;
        int rem = idx & 65535;
        int k = rem >> 9, c = rem & 511;
        float v;
        if (c < 128)      v = pcW1[l*32768 + k*128 + c];
        else if (c < 256) v = pcW1[l*32768 + (128+k)*128 + (c-128)];
        else if (c < 384) v = preW[l*49152 + k*128 + (c-256)];
        else              v = preW[l*49152 + (128+k)*128 + (c-384)];
        __nv_bfloat16 h, lo; split_bf(v, h, lo);
        g_WxI[idx] = h; g_WxI[327680 + idx] = lo;
        if (idx < 2560) {
            int ll = idx >> 9, cc = idx & 511;
            float b = 0.f;
            if (cc >= 128 && cc < 256) b = pcB1[ll*128 + (cc-128)];
            else if (cc >= 384)        b = preB[ll*128 + (cc-384)];
            g_bx[idx] = b;
        }
        return;
    }
    idx -= 327680;
    if (idx < 737280) {
        int l = (int)(idx / 147456);
        int rem = (int)(idx - (long)l*147456);
        int r = rem >> 7, j = rem & 127;
        const float* Wl = postW + (size_t)l*409600;
        float log5 = logf(5.f), log17 = logf(17.f);
        float v;
        if (r < 128) {
            v = Wl[r*128 + j] + ((r == j) ? 1.f : 0.f);
        } else if (r < 640) {
            int rp = r - 128;
            v = Wl[(128+rp)*128+j] + log5*Wl[(640+rp)*128+j] + Wl[(1152+rp)*128+j]*(1.f/log5);
        } else {
            int rp = r - 640;
            v = Wl[(1664+rp)*128+j] + log17*Wl[(2176+rp)*128+j] + Wl[(2688+rp)*128+j]*(1.f/log17);
        }
        __nv_bfloat16 h, lo; split_bf(v, h, lo);
        g_WeI[idx] = h; g_WeI[737280 + idx] = lo;
        return;
    }
    idx -= 737280;
    if (idx < 81920) {
        int l = (int)(idx >> 14), rem = (int)(idx & 16383);
        float v = pcW2[l*16384 + rem];
        __nv_bfloat16 h, lo; split_bf(v, h, lo);
        unsigned char* base = g_Bimg + (size_t)l*65536;
        *(__nv_bfloat16*)(base + rem*2)         = h;
        *(__nv_bfloat16*)(base + 32768 + rem*2) = lo;
        return;
    }
    idx -= 81920;
    if (idx < 81920) {
        int l = (int)(idx >> 14), rem = (int)(idx & 16383);
        float v = preW[l*49152 + 32768 + rem];
        __nv_bfloat16 h, lo; split_bf(v, h, lo);
        g_P3I[idx] = h; g_P3I[81920 + idx] = lo;
        return;
    }
    idx -= 81920;
    if (idx < 16384) {
        __nv_bfloat16 h, lo; split_bf(onW1[idx], h, lo);
        g_OnI[idx] = h; g_OnI[16384 + idx] = lo;
        return;
    }
    idx -= 16384;
    if (idx < 16384) {
        __nv_bfloat16 h, lo; split_bf(onW2[idx], h, lo);
        g_OnI[32768 + idx] = h; g_OnI[49152 + idx] = lo;
    }
}

// ---------------- scalar input GEMM -> bf16 hi/lo image output ----------------
__global__ __launch_bounds__(256) void gemm_in_kernel(
    const float* __restrict__ A, int lda,
    const float* __restrict__ W, const float* __restrict__ bias,
    __nv_bfloat16* __restrict__ outH, __nv_bfloat16* __restrict__ outL, int K)
{
    __shared__ float As[16][64];
    __shared__ float Bs[16][128];
    const int t  = threadIdx.x;
    const int m0 = blockIdx.x * 64;
    const int tc = t & 31, tr = t >> 5;
    const int ar = t >> 2;
    const int akq = (t & 3) << 2;

    float acc[8][4];
#pragma unroll
    for (int i = 0; i < 8; i++)
#pragma unroll
        for (int c = 0; c < 4; c++) acc[i][c] = 0.f;

    for (int k0 = 0; k0 < K; k0 += 16) {
        int kg = k0 + akq;
        float4 av = *(const float4*)(A + (size_t)(m0 + ar)*lda + kg);
        As[akq+0][ar] = av.x; As[akq+1][ar] = av.y;
        As[akq+2][ar] = av.z; As[akq+3][ar] = av.w;
#pragma unroll
        for (int i = 0; i < 2; i++) {
            int off = t*8 + i*4;
            int kk = off >> 7, j = off & 127;
            *(float4*)&Bs[kk][j] = *(const float4*)&W[(size_t)(k0+kk)*128 + j];
        }
        __syncthreads();
#pragma unroll
        for (int kk = 0; kk < 16; kk++) {
            float a[8];
            *(float4*)&a[0] = *(const float4*)&As[kk][tr*8];
            *(float4*)&a[4] = *(const float4*)&As[kk][tr*8+4];
            float4 b = *(const float4*)&Bs[kk][tc*4];
#pragma unroll
            for (int i = 0; i < 8; i++) {
                acc[i][0] += a[i]*b.x; acc[i][1] += a[i]*b.y;
                acc[i][2] += a[i]*b.z; acc[i][3] += a[i]*b.w;
            }
        }
        __syncthreads();
    }
    float4 b4 = *(const float4*)&bias[tc*4];
    float bv[4] = {b4.x, b4.y, b4.z, b4.w};
#pragma unroll
    for (int i = 0; i < 8; i++) {
        ushort2 hh[2], ll[2];
#pragma unroll
        for (int c = 0; c < 4; c++) {
            float v = fmaxf(acc[i][c] + bv[c], 0.f);
            __nv_bfloat16 h, lo; split_bf(v, h, lo);
            ((unsigned short*)hh)[c] = __bfloat16_as_ushort(h);
            ((unsigned short*)ll)[c] = __bfloat16_as_ushort(lo);
        }
        size_t o = (size_t)(m0 + tr*8 + i)*128 + tc*4;
        *(uint2*)&outH[o] = *(uint2*)hh;
        *(uint2*)&outL[o] = *(uint2*)ll;
    }
}

// ---------------- tensor GEMM: bf16 hi/lo images, NS-stage cp.async pipeline ----------------
// blockIdx.z selects a "layer": B advances bz per z, fp32 out advances oz per z.
template<bool RELU, int TM, bool IMG, int NS>
__global__ __launch_bounds__(256) void tgemm_bf(
    const __nv_bfloat16* __restrict__ A0H, const __nv_bfloat16* __restrict__ A0L, int lda0,
    const __nv_bfloat16* __restrict__ A1H, const __nv_bfloat16* __restrict__ A1L, int lda1, int Ksplit,
    const __nv_bfloat16* __restrict__ BH, const __nv_bfloat16* __restrict__ BL, int ldb,
    const float* __restrict__ bias,
    float* __restrict__ outF, __nv_bfloat16* __restrict__ outH, __nv_bfloat16* __restrict__ outL,
    int ldo, int K, int bz, int oz)
{
    constexpr int NT = (TM == 128) ? 16 : 8;
    constexpr int ASTG = TM*40*2;
    constexpr int ASTAGE = 2*ASTG;
    constexpr int BIMG = 32*136*2;
    constexpr int BSTAGE = 2*BIMG;
    extern __shared__ __align__(16) char smem[];
    char* sA = smem;
    char* sB = smem + NS*ASTAGE;
    float* sBias = (float*)(smem + NS*ASTAGE + NS*BSTAGE);

    const int z = blockIdx.z;
    BH += (size_t)z * bz;
    BL += (size_t)z * bz;
    if (outF) outF += (size_t)z * oz;

    const int t = threadIdx.x;
    const int w = t >> 5, lid = t & 31;
    const int m0 = blockIdx.x * TM;
    const int n0 = blockIdx.y * 128;
    const int WR = (TM == 128) ? w : (w & 3);
    const int WC = (TM == 128) ? 0 : (w >> 2);

    if (t < 128) sBias[t] = bias ? bias[n0 + t] : 0.f;

    const uint32_t sAb = smem_to_u32(sA);
    const uint32_t sBb = smem_to_u32(sB);

    int arow, acol;
    if (TM == 128) { arow = t >> 1; acol = (t & 1) * 16; }
    else           { arow = t >> 2; acol = (t & 3) * 8; }
    const int bk = t >> 3, bu = (t & 7) * 16;

    auto issue = [&](int kc, int st) {
        int k0 = kc * 32;
        int kg = k0 + acol;
        const __nv_bfloat16 *pH, *pL;
        if (kg < Ksplit) {
            pH = A0H + (size_t)(m0 + arow)*lda0 + kg;
            pL = A0L + (size_t)(m0 + arow)*lda0 + kg;
        } else {
            pH = A1H + (size_t)(m0 + arow)*lda1 + (kg - Ksplit);
            pL = A1L + (size_t)(m0 + arow)*lda1 + (kg - Ksplit);
        }
        uint32_t ad = sAb + st*ASTAGE + (uint32_t)(arow*40 + acol)*2;
        CPA16(ad, pH);
        CPA16(ad + ASTG, pL);
        if (TM == 128) {
            CPA16(ad + 16, pH + 8);
            CPA16(ad + ASTG + 16, pL + 8);
        }
        const __nv_bfloat16* qH = BH + (size_t)(k0 + bk)*ldb + n0 + bu;
        const __nv_bfloat16* qL = BL + (size_t)(k0 + bk)*ldb + n0 + bu;
        uint32_t bd = sBb + st*BSTAGE + (uint32_t)(bk*136 + bu)*2;
        CPA16(bd, qH); CPA16(bd + 16, qH + 8);
        CPA16(bd + BIMG, qL); CPA16(bd + BIMG + 16, qL + 8);
    };

    float acc[NT][4];
#pragma unroll
    for (int nt = 0; nt < NT; nt++)
#pragma unroll
        for (int r = 0; r < 4; r++) acc[nt][r] = 0.f;

    const uint32_t a_off = (uint32_t)((16*WR + (lid & 15))*40 + (lid >> 4)*8) * 2;
    const uint32_t b_off = (uint32_t)(((lid & 7) + ((lid >> 3) & 1)*8)*136 + (lid >> 4)*8 + WC*64) * 2;

    const int nk = K / 32;
#pragma unroll
    for (int s = 0; s < NS-1; s++) {
        if (s < nk) issue(s, s);
        CPC();
    }
    for (int kc = 0; kc < nk; kc++) {
        int st = kc % NS;
        asm volatile("cp.async.wait_group %0;" :: "n"(NS-2) : "memory");
        __syncthreads();
        int kn = kc + NS - 1;
        if (kn < nk) issue(kn, kn % NS);
        CPC();
        uint32_t aH = sAb + st*ASTAGE + a_off;
        uint32_t aL = aH + ASTG;
        uint32_t bHb = sBb + st*BSTAGE + b_off;
        uint32_t bLb = bHb + BIMG;
#pragma unroll
        for (int kh = 0; kh < 2; kh++) {
            uint32_t aH0,aH1,aH2,aH3, aL0,aL1,aL2,aL3;
            LDSM_X4(aH0,aH1,aH2,aH3, aH + kh*32);
            LDSM_X4(aL0,aL1,aL2,aL3, aL + kh*32);
#pragma unroll
            for (int jg = 0; jg < NT/4; jg++) {
                uint32_t bo = kh*4352 + jg*64;
                uint32_t bh0,bh1,bh2,bh3, bh4,bh5,bh6,bh7;
                uint32_t bl0,bl1,bl2,bl3, bl4,bl5,bl6,bl7;
                LDSM_X4_T(bh0,bh1,bh2,bh3, bHb + bo);
                LDSM_X4_T(bh4,bh5,bh6,bh7, bHb + bo + 32);
                LDSM_X4_T(bl0,bl1,bl2,bl3, bLb + bo);
                LDSM_X4_T(bl4,bl5,bl6,bl7, bLb + bo + 32);
                MMA_BF16(acc[4*jg+0], aH0,aH1,aH2,aH3, bh0,bh1);
                MMA_BF16(acc[4*jg+0], aL0,aL1,aL2,aL3, bh0,bh1);
                MMA_BF16(acc[4*jg+0], aH0,aH1,aH2,aH3, bl0,bl1);
                MMA_BF16(acc[4*jg+1], aH0,aH1,aH2,aH3, bh2,bh3);
                MMA_BF16(acc[4*jg+1], aL0,aL1,aL2,aL3, bh2,bh3);
                MMA_BF16(acc[4*jg+1], aH0,aH1,aH2,aH3, bl2,bl3);
                MMA_BF16(acc[4*jg+2], aH0,aH1,aH2,aH3, bh4,bh5);
                MMA_BF16(acc[4*jg+2], aL0,aL1,aL2,aL3, bh4,bh5);
                MMA_BF16(acc[4*jg+2], aH0,aH1,aH2,aH3, bl4,bl5);
                MMA_BF16(acc[4*jg+3], aH0,aH1,aH2,aH3, bh6,bh7);
                MMA_BF16(acc[4*jg+3], aL0,aL1,aL2,aL3, bh6,bh7);
                MMA_BF16(acc[4*jg+3], aH0,aH1,aH2,aH3, bl6,bl7);
            }
        }
    }

    __syncthreads();
    const int r0 = 16*WR + (lid >> 2), r1 = r0 + 8;
    const int cb = 2*(lid & 3);
#pragma unroll
    for (int nt = 0; nt < NT; nt++) {
        int c0 = WC*64 + 8*nt + cb;
        float b0 = sBias[c0], b1 = sBias[c0+1];
        float v0 = acc[nt][0] + b0, v1 = acc[nt][1] + b1;
        float v2 = acc[nt][2] + b0, v3 = acc[nt][3] + b1;
        if (RELU) {
            v0 = fmaxf(v0, 0.f); v1 = fmaxf(v1, 0.f);
            v2 = fmaxf(v2, 0.f); v3 = fmaxf(v3, 0.f);
        }
        if (IMG) {
            __nv_bfloat16 h0,l0,h1,l1,h2,l2,h3,l3;
            split_bf(v0, h0, l0); split_bf(v1, h1, l1);
            split_bf(v2, h2, l2); split_bf(v3, h3, l3);
            *(uint32_t*)&outH[(size_t)(m0 + r0)*ldo + n0 + c0] =
                ((uint32_t)__bfloat16_as_ushort(h1) << 16) | __bfloat16_as_ushort(h0);
            *(uint32_t*)&outL[(size_t)(m0 + r0)*ldo + n0 + c0] =
                ((uint32_t)__bfloat16_as_ushort(l1) << 16) | __bfloat16_as_ushort(l0);
            *(uint32_t*)&outH[(size_t)(m0 + r1)*ldo + n0 + c0] =
                ((uint32_t)__bfloat16_as_ushort(h3) << 16) | __bfloat16_as_ushort(h2);
            *(uint32_t*)&outL[(size_t)(m0 + r1)*ldo + n0 + c0] =
                ((uint32_t)__bfloat16_as_ushort(l3) << 16) | __bfloat16_as_ushort(l2);
        } else {
            *(float2*)&outF[(size_t)(m0 + r0)*ldo + n0 + c0] = make_float2(v0, v1);
            *(float2*)&outF[(size_t)(m0 + r1)*ldo + n0 + c0] = make_float2(v2, v3);
        }
    }
}

// ---------------- fused comp-edge kernel + bond tail: 2x128-edge subtiles per block ----------
#define CS_MS    0                    // 128 x 132 f32 = 67584
#define CS_GS    67584                // 512
#define CS_B2    68096                // 512
#define CS_SEW   68608                // 512
#define CS_AH    69120                // 128 x 136 bf16 = 34816
#define CS_AL    103936
#define CS_BH    138752
#define CS_BL    173568
#define CS_TOTAL 208384

__global__ __launch_bounds__(256, 1) void comp_kernel(
    const int* __restrict__ src,
    const int* __restrict__ bsrc,
    int layer,
    const float* __restrict__ b2,
    const float* __restrict__ seW,
    const float* __restrict__ seB)
{
    extern __shared__ __align__(16) char smem[];
    const uint32_t sb = smem_to_u32(smem);
    const int t = threadIdx.x;
    const int w = t >> 5, lid = t & 31;

    float* sM  = (float*)(smem + CS_MS);
    float* sG  = (float*)(smem + CS_GS);
    float* sb2 = (float*)(smem + CS_B2);
    float* ssw = (float*)(smem + CS_SEW);

    if (t < 128) {
        sb2[t] = b2[t];
        ssw[t] = seW[t];
    }

    {   // copy W2 hi/lo images into padded smem [k][136]  (ONCE per block)
        int row = t >> 1, half = t & 1;
        const uint4* srcH = (const uint4*)(g_Bimg + (size_t)layer*65536 + row*256 + half*128);
        const uint4* srcL = (const uint4*)(g_Bimg + (size_t)layer*65536 + 32768 + row*256 + half*128);
        uint4* dstH = (uint4*)(smem + CS_BH + row*272 + half*128);
        uint4* dstL = (uint4*)(smem + CS_BL + row*272 + half*128);
#pragma unroll
        for (int i = 0; i < 8; i++) { dstH[i] = srcH[i]; dstL[i] = srcL[i]; }
    }

    const uint32_t a_addr = sb + CS_AH + (uint32_t)((16*w + (lid & 15)) * 136 + (lid >> 4) * 8) * 2;
    const uint32_t b_addr = sb + CS_BH + (uint32_t)(((lid & 7) + ((lid >> 3) & 1) * 8) * 136 + (lid >> 4) * 8) * 2;

    for (int sub = 0; sub < 2; sub++) {
        const int e0 = blockIdx.x * 256 + sub * 128;

        {   // build A tile: gather + add + relu, bf16 hi/lo
            int row = t >> 1, half = t & 1;
            int s = src[e0 + row];
            int node = (e0 >> 4) + (row >> 4);
            const float* x1 = g_X + (size_t)s*512 + half*64;
            const float* x2 = g_X + (size_t)node*512 + 128 + half*64;
            uint32_t* ah = (uint32_t*)(smem + CS_AH + row*272 + half*128);
            uint32_t* al = (uint32_t*)(smem + CS_AL + row*272 + half*128);
#pragma unroll
            for (int i = 0; i < 64; i += 4) {
                float4 a = *(const float4*)(x1 + i);
                float4 b = *(const float4*)(x2 + i);
                float v0 = fmaxf(a.x + b.x, 0.f), v1 = fmaxf(a.y + b.y, 0.f);
                float v2 = fmaxf(a.z + b.z, 0.f), v3 = fmaxf(a.w + b.w, 0.f);
                __nv_bfloat16 h0,l0,h1,l1,h2,l2,h3,l3;
                split_bf(v0,h0,l0); split_bf(v1,h1,l1);
                split_bf(v2,h2,l2); split_bf(v3,h3,l3);
                ah[i/2]   = ((uint32_t)__bfloat16_as_ushort(h1) << 16) | __bfloat16_as_ushort(h0);
                ah[i/2+1] = ((uint32_t)__bfloat16_as_ushort(h3) << 16) | __bfloat16_as_ushort(h2);
                al[i/2]   = ((uint32_t)__bfloat16_as_ushort(l1) << 16) | __bfloat16_as_ushort(l0);
                al[i/2+1] = ((uint32_t)__bfloat16_as_ushort(l3) << 16) | __bfloat16_as_ushort(l2);
            }
        }
        __syncthreads();

        float acc[16][4];
#pragma unroll
        for (int nt = 0; nt < 16; nt++)
#pragma unroll
            for (int r = 0; r < 4; r++) acc[nt][r] = 0.f;

        for (int ks = 0; ks < 8; ks++) {
            uint32_t aH0,aH1,aH2,aH3, aL0,aL1,aL2,aL3;
            uint32_t aoff = a_addr + ks*32;
            LDSM_X4(aH0,aH1,aH2,aH3, aoff);
            LDSM_X4(aL0,aL1,aL2,aL3, aoff + (CS_AL - CS_AH));
#pragma unroll
            for (int jg = 0; jg < 4; jg++) {
                uint32_t bofs = b_addr + ks*4352 + jg*64;
                uint32_t bh0,bh1,bh2,bh3, bh4,bh5,bh6,bh7;
                uint32_t bl0,bl1,bl2,bl3, bl4,bl5,bl6,bl7;
                LDSM_X4_T(bh0,bh1,bh2,bh3, bofs);
                LDSM_X4_T(bh4,bh5,bh6,bh7, bofs + 32);
                LDSM_X4_T(bl0,bl1,bl2,bl3, bofs + (CS_BL - CS_BH));
                LDSM_X4_T(bl4,bl5,bl6,bl7, bofs + (CS_BL - CS_BH) + 32);
                MMA_BF16(acc[4*jg+0], aH0,aH1,aH2,aH3, bh0,bh1);
                MMA_BF16(acc[4*jg+0], aL0,aL1,aL2,aL3, bh0,bh1);
                MMA_BF16(acc[4*jg+0], aH0,aH1,aH2,aH3, bl0,bl1);
                MMA_BF16(acc[4*jg+1], aH0,aH1,aH2,aH3, bh2,bh3);
                MMA_BF16(acc[4*jg+1], aL0,aL1,aL2,aL3, bh2,bh3);
                MMA_BF16(acc[4*jg+1], aH0,aH1,aH2,aH3, bl2,bl3);
                MMA_BF16(acc[4*jg+2], aH0,aH1,aH2,aH3, bh4,bh5);
                MMA_BF16(acc[4*jg+2], aL0,aL1,aL2,aL3, bh4,bh5);
                MMA_BF16(acc[4*jg+2], aH0,aH1,aH2,aH3, bl4,bl5);
                MMA_BF16(acc[4*jg+3], aH0,aH1,aH2,aH3, bh6,bh7);
                MMA_BF16(acc[4*jg+3], aL0,aL1,aL2,aL3, bh6,bh7);
                MMA_BF16(acc[4*jg+3], aH0,aH1,aH2,aH3, bl6,bl7);
            }
        }

        {   // epilogue: bias + gate partials + stage to sM
            int r0 = 16*w + (lid >> 2);
            int r1 = r0 + 8;
            int cb = 2*(lid & 3);
            float p0 = 0.f, p1 = 0.f;
#pragma unroll
            for (int nt = 0; nt < 16; nt++) {
                int c0 = 8*nt + cb;
                float bb0 = sb2[c0], bb1 = sb2[c0+1];
                float w0 = ssw[c0], w1 = ssw[c0+1];
                float m0 = acc[nt][0] + bb0, m1 = acc[nt][1] + bb1;
                float m2 = acc[nt][2] + bb0, m3 = acc[nt][3] + bb1;
                p0 += m0*w0 + m1*w1;
                p1 += m2*w0 + m3*w1;
                sM[r0*132 + c0]     = m0;
                sM[r0*132 + c0 + 1] = m1;
                sM[r1*132 + c0]     = m2;
                sM[r1*132 + c0 + 1] = m3;
            }
            p0 += __shfl_xor_sync(0xffffffffu, p0, 1);
            p0 += __shfl_xor_sync(0xffffffffu, p0, 2);
            p1 += __shfl_xor_sync(0xffffffffu, p1, 1);
            p1 += __shfl_xor_sync(0xffffffffu, p1, 2);
            if ((lid & 3) == 0) {
                float sbv = seB[0];
                sG[r0] = 1.f / (1.f + expf(-(p0 + sbv)));
                sG[r1] = 1.f / (1.f + expf(-(p1 + sbv)));
            }
        }
        __syncthreads();

        // PNA stats: 8 nodes x 128 cols, write bf16 hi/lo agg images
#pragma unroll
        for (int q = 0; q < 4; q++) {
            int item = q*256 + t;
            int n8 = item >> 7, col = item & 127;
            float s = 0.f, sq = 0.f, mx = -INFINITY, mn = INFINITY;
#pragma unroll
            for (int i = 0; i < 16; i++) {
                int row = n8*16 + i;
                float v = sM[row*132 + col] * sG[row];
                s += v; sq += v*v; mx = fmaxf(mx, v); mn = fminf(mn, v);
            }
            int node = (e0 >> 4) + n8;
            float mean = s * 0.0625f;
            float sd = sqrtf(fmaxf(sq*0.0625f - mean*mean, 0.f) + 1e-5f);
            size_t base = (size_t)node*1024 + 512 + col;
            float vs[4] = {mean, mx, mn, sd};
#pragma unroll
            for (int z = 0; z < 4; z++) {
                __nv_bfloat16 h, lo; split_bf(vs[z], h, lo);
                g_aggI[base + z*128]        = h;
                g_aggI[AGGN + base + z*128] = lo;
            }
        }
        __syncthreads();   // before next subtile overwrites A / sM / sG
    }

    // ---- bond PNA tail for this block's 16 nodes (2048 col-items, 8/thread) ----
    {
        const float* Cl = g_C5 + (size_t)layer * EB * 128;
        const int nb0 = blockIdx.x * 16;
#pragma unroll
        for (int q = 0; q < 8; q++) {
            int item = q*256 + t;
            int nl = item >> 7, j = item & 127;
            int n = nb0 + nl;
            float base = g_X[(size_t)n*512 + 384 + j];
            float s=0.f, sq=0.f, mx=-INFINITY, mn=INFINITY;
#pragma unroll
            for (int e = 0; e < 4; e++) {
                int ei = n*4 + e;
                int sv = bsrc[ei];
                float v = g_X[(size_t)sv*512 + 256 + j] + base + Cl[(size_t)ei*128 + j];
                s += v; sq += v*v; mx = fmaxf(mx, v); mn = fminf(mn, v);
            }
            float mean = s*0.25f;
            float sd = sqrtf(fmaxf(sq*0.25f - mean*mean, 0.f) + 1e-5f);
            size_t ob = (size_t)n*1024 + j;
            float vs[4] = {mean, mx, mn, sd};
#pragma unroll
            for (int z = 0; z < 4; z++) {
                __nv_bfloat16 h, lo; split_bf(vs[z], h, lo);
                g_aggI[ob + z*128]        = h;
                g_aggI[AGGN + ob + z*128] = lo;
            }
        }
    }
}

// ---------------- readout ----------------
__global__ __launch_bounds__(128) void readout_kernel(
    const float* __restrict__ h3,
    const float* __restrict__ W1, const float* __restrict__ b1,
    const float* __restrict__ W2, const float* __restrict__ b2,
    float* __restrict__ out)
{
    __shared__ float r[384];
    __shared__ float tb[128];
    int g = blockIdx.x, j = threadIdx.x;
    const float* p = h3 + (size_t)g*100*128 + j;
    float s = 0.f, mx = -INFINITY;
    for (int i = 0; i < 100; i++) {
        float v = p[i*128];
        s += v; mx = fmaxf(mx, v);
    }
    r[j] = s; r[128+j] = s/100.f; r[256+j] = mx;
    __syncthreads();
    float a = b1[j];
    for (int k = 0; k < 384; k++) a += r[k]*W1[k*128 + j];
    tb[j] = fmaxf(a, 0.f);
    __syncthreads();
    if (j < 32) {
        float o = b2[j];
        for (int k = 0; k < 128; k++) o += tb[k]*W2[k*32 + j];
        out[g*32 + j] = o;
    }
}

// ---------------- launcher ----------------
extern "C" void kernel_launch(void* const* d_in, const int* in_sizes, int n_in,
                              void* d_out, int out_size) {
    const float* node_feat = (const float*)d_in[0];
    const float* edge_feat = (const float*)d_in[1];
    const int*   bond_src  = (const int*)d_in[2];
    const int*   comp_src  = (const int*)d_in[4];
    const float* in_W   = (const float*)d_in[7];
    const float* in_b   = (const float*)d_in[8];
    const float* ein_W  = (const float*)d_in[9];
    const float* ein_b  = (const float*)d_in[10];
    const float* pre_W  = (const float*)d_in[11];
    const float* pre_b  = (const float*)d_in[12];
    const float* pc_W1  = (const float*)d_in[13];
    const float* pc_b1  = (const float*)d_in[14];
    const float* pc_W2  = (const float*)d_in[15];
    const float* pc_b2  = (const float*)d_in[16];
    const float* se_W   = (const float*)d_in[17];
    const float* se_b   = (const float*)d_in[18];
    const float* post_W = (const float*)d_in[19];
    const float* post_b = (const float*)d_in[20];
    const float* outn_W1 = (const float*)d_in[21];
    const float* outn_b1 = (const float*)d_in[22];
    const float* outn_W2 = (const float*)d_in[23];
    const float* outn_b2 = (const float*)d_in[24];
    const float* ro_W1 = (const float*)d_in[25];
    const float* ro_b1 = (const float*)d_in[26];
    const float* ro_W2 = (const float*)d_in[27];
    const float* ro_b2 = (const float*)d_in[28];

    float *hA, *X, *C5, *bx;
    __nv_bfloat16 *WxI, *P3I, *WeI, *OnI, *hIA, *hIB, *efI, *aggI, *t1I;
    cudaGetSymbolAddress((void**)&hA, g_hA);
    cudaGetSymbolAddress((void**)&X,  g_X);
    cudaGetSymbolAddress((void**)&C5, g_C5);
    cudaGetSymbolAddress((void**)&bx, g_bx);
    cudaGetSymbolAddress((void**)&WxI, g_WxI);
    cudaGetSymbolAddress((void**)&P3I, g_P3I);
    cudaGetSymbolAddress((void**)&WeI, g_WeI);
    cudaGetSymbolAddress((void**)&OnI, g_OnI);
    cudaGetSymbolAddress((void**)&hIA, g_hImgA);
    cudaGetSymbolAddress((void**)&hIB, g_hImgB);
    cudaGetSymbolAddress((void**)&efI, g_efI);
    cudaGetSymbolAddress((void**)&aggI, g_aggI);
    cudaGetSymbolAddress((void**)&t1I, g_t1I);

    const int SM128 = 2*(2*128*40*2) + 2*(2*32*136*2) + 512;   // 76288
    const int SM64  = 3*(2*64*40*2)  + 3*(2*32*136*2) + 512;   // 83456
    cudaFuncSetAttribute(comp_kernel, cudaFuncAttributeMaxDynamicSharedMemorySize, CS_TOTAL);
    cudaFuncSetAttribute(tgemm_bf<false,128,false,2>, cudaFuncAttributeMaxDynamicSharedMemorySize, SM128);
    cudaFuncSetAttribute(tgemm_bf<false,64,true,3>,  cudaFuncAttributeMaxDynamicSharedMemorySize, SM64);
    cudaFuncSetAttribute(tgemm_bf<true,64,true,3>,   cudaFuncAttributeMaxDynamicSharedMemorySize, SM64);
    cudaFuncSetAttribute(tgemm_bf<false,64,false,3>, cudaFuncAttributeMaxDynamicSharedMemorySize, SM64);

    pack_all_kernel<<<4928, 256>>>(pc_W1, pre_W, pc_b1, pre_b, post_W, pc_W2, outn_W1, outn_W2);

    // input transforms -> bf16 hi/lo images
    gemm_in_kernel<<<NN/64, 256>>>(node_feat, 64, in_W, in_b, hIA, hIA + NN*128, 64);
    gemm_in_kernel<<<EB/64, 256>>>(edge_feat, 16, ein_W, ein_b, efI, efI + EB*128, 16);

    // C for ALL 5 layers in one launch (ef constant across layers)
    tgemm_bf<false,128,false,2><<<dim3(EB/128, 1, 5), 256, SM128>>>(
        efI, efI + EB*128, 128, efI, efI + EB*128, 128, 128,
        P3I, P3I + 5*16384, 128,
        nullptr, C5, nullptr, nullptr, 128, 128, 16384, EB*128);

    __nv_bfloat16* cur = hIA;   // hi at cur, lo at cur + NN*128
    __nv_bfloat16* nxt = hIB;
    for (int l = 0; l < 5; l++) {
        // X = h @ [W1a | W1b | P1 | P2] + [0 | b1 | 0 | preb]  (fp32 out)
        tgemm_bf<false,128,false,2><<<dim3(NN/128, 4, 1), 256, SM128>>>(
            cur, cur + NN*128, 128, cur, cur + NN*128, 128, 128,
            WxI + l*65536, WxI + 5*65536 + l*65536, 512,
            bx + l*512, X, nullptr, nullptr, 512, 128, 0, 0);
        // comp edges (incl. bond PNA tail)
        comp_kernel<<<EC/256, 256, CS_TOTAL>>>(comp_src, bond_src, l, pc_b2 + l*128,
                                               se_W + l*128, se_b + l);
        // h_next = [h | agg] @ W_eff + post_b  (image out, residual+scalers folded)
        tgemm_bf<false,64,true,3><<<dim3(NN/64, 1, 1), 256, SM64>>>(
            cur, cur + NN*128, 128, aggI, aggI + AGGN, 1024, 128,
            WeI + l*147456, WeI + 5*147456 + l*147456, 128,
            post_b + l*128, nullptr, nxt, nxt + NN*128, 128, 1152, 0, 0);
        __nv_bfloat16* tmp = cur; cur = nxt; nxt = tmp;
    }

    // node-wise output MLP
    tgemm_bf<true,64,true,3><<<dim3(NN/64, 1, 1), 256, SM64>>>(
        cur, cur + NN*128, 128, cur, cur + NN*128, 128, 128,
        OnI, OnI + 16384, 128,
        outn_b1, nullptr, t1I, t1I + NN*128, 128, 128, 0, 0);
    tgemm_bf<false,64,false,3><<<dim3(NN/64, 1, 1), 256, SM64>>>(
        t1I, t1I + NN*128, 128, t1I, t1I + NN*128, 128, 128,
        OnI + 32768, OnI + 49152, 128,
        outn_b2, hA, nullptr, nullptr, 128, 128, 0, 0);
    // readout
    readout_kernel<<<GG, 128>>>(hA, ro_W1, ro_b1, ro_W2, ro_b2, (float*)d_out);
}

// round 17
// speedup vs baseline: 1.0952x; 1.0952x over previous
#include <cuda_runtime.h>
#include <cuda_bf16.h>
#include <cstdint>
#include <math.h>

#define NN 12800
#define GG 128
#define EB 51200
#define EC 204800
#define AGGN (NN*1024)

__device__ __forceinline__ uint32_t smem_to_u32(const void* p) {
    uint32_t a;
    asm("{ .reg .u64 t; cvta.to.shared.u64 t, %1; cvt.u32.u64 %0, t; }" : "=r"(a) : "l"(p));
    return a;
}
#define LDSM_X4(r0,r1,r2,r3, addr) \
    asm volatile("ldmatrix.sync.aligned.m8n8.x4.shared.b16 {%0,%1,%2,%3}, [%4];" \
        : "=r"(r0),"=r"(r1),"=r"(r2),"=r"(r3) : "r"(addr))
#define LDSM_X4_T(r0,r1,r2,r3, addr) \
    asm volatile("ldmatrix.sync.aligned.m8n8.x4.trans.shared.b16 {%0,%1,%2,%3}, [%4];" \
        : "=r"(r0),"=r"(r1),"=r"(r2),"=r"(r3) : "r"(addr))
#define MMA_BF16(d, a0,a1,a2,a3, b0,b1) \
    asm volatile("mma.sync.aligned.m16n8k16.row.col.f32.bf16.bf16.f32 " \
        "{%0,%1,%2,%3}, {%4,%5,%6,%7}, {%8,%9}, {%0,%1,%2,%3};" \
        : "+f"((d)[0]),"+f"((d)[1]),"+f"((d)[2]),"+f"((d)[3]) \
        : "r"(a0),"r"(a1),"r"(a2),"r"(a3), "r"(b0),"r"(b1))
#define CPA16(dst, src) \
    asm volatile("cp.async.cg.shared.global [%0], [%1], 16;" :: "r"(dst), "l"(src))
#define CPC() asm volatile("cp.async.commit_group;" ::: "memory")

// ---------------- scratch (no allocations allowed) ----------------
__device__ float g_hA[NN*128];     // final node output fp32 (readout input)
__device__ float g_X[NN*512];      // [A1 | A2+b1 | B1 | B2+preb] per node
__device__ float g_C5[5*EB*128];   // ef @ P3, all 5 layers (computed upfront)
__device__ float g_bx[5*512];
__device__ __align__(16) unsigned char g_Bimg[5*65536];       // W2 bf16 hi+lo per layer (comp)
__device__ __align__(16) __nv_bfloat16 g_WxI[2*5*65536];
__device__ __align__(16) __nv_bfloat16 g_P3I[2*5*16384];
__device__ __align__(16) __nv_bfloat16 g_WeI[2*5*147456];
__device__ __align__(16) __nv_bfloat16 g_OnI[4*16384];        // hiW1 | loW1 | hiW2 | loW2
__device__ __align__(16) __nv_bfloat16 g_hImgA[2*NN*128];
__device__ __align__(16) __nv_bfloat16 g_hImgB[2*NN*128];
__device__ __align__(16) __nv_bfloat16 g_efI[2*EB*128];
__device__ __align__(16) __nv_bfloat16 g_aggI[2*NN*1024];     // hi then lo
__device__ __align__(16) __nv_bfloat16 g_t1I[2*NN*128];

__device__ __forceinline__ void split_bf(float v, __nv_bfloat16& h, __nv_bfloat16& l) {
    h = __float2bfloat16(v);
    l = __float2bfloat16(v - __bfloat162float(h));
}

// ---------------- ONE merged weight-pack kernel (all images) ----------------
__global__ void pack_all_kernel(
    const float* __restrict__ pcW1, const float* __restrict__ preW,
    const float* __restrict__ pcB1, const float* __restrict__ preB,
    const float* __restrict__ postW, const float* __restrict__ pcW2,
    const float* __restrict__ onW1, const float* __restrict__ onW2)
{
    long idx = (long)blockIdx.x * 256 + threadIdx.x;
    if (idx < 327680) {
        int l = idx >> 16;
        int rem = idx & 65535;
        int k = rem >> 9, c = rem & 511;
        float v;
        if (c < 128)      v = pcW1[l*32768 + k*128 + c];
        else if (c < 256) v = pcW1[l*32768 + (128+k)*128 + (c-128)];
        else if (c < 384) v = preW[l*49152 + k*128 + (c-256)];
        else              v = preW[l*49152 + (128+k)*128 + (c-384)];
        __nv_bfloat16 h, lo; split_bf(v, h, lo);
        g_WxI[idx] = h; g_WxI[327680 + idx] = lo;
        if (idx < 2560) {
            int ll = idx >> 9, cc = idx & 511;
            float b = 0.f;
            if (cc >= 128 && cc < 256) b = pcB1[ll*128 + (cc-128)];
            else if (cc >= 384)        b = preB[ll*128 + (cc-384)];
            g_bx[idx] = b;
        }
        return;
    }
    idx -= 327680;
    if (idx < 737280) {
        int l = (int)(idx / 147456);
        int rem = (int)(idx - (long)l*147456);
        int r = rem >> 7, j = rem & 127;
        const float* Wl = postW + (size_t)l*409600;
        float log5 = logf(5.f), log17 = logf(17.f);
        float v;
        if (r < 128) {
            v = Wl[r*128 + j] + ((r == j) ? 1.f : 0.f);
        } else if (r < 640) {
            int rp = r - 128;
            v = Wl[(128+rp)*128+j] + log5*Wl[(640+rp)*128+j] + Wl[(1152+rp)*128+j]*(1.f/log5);
        } else {
            int rp = r - 640;
            v = Wl[(1664+rp)*128+j] + log17*Wl[(2176+rp)*128+j] + Wl[(2688+rp)*128+j]*(1.f/log17);
        }
        __nv_bfloat16 h, lo; split_bf(v, h, lo);
        g_WeI[idx] = h; g_WeI[737280 + idx] = lo;
        return;
    }
    idx -= 737280;
    if (idx < 81920) {
        int l = (int)(idx >> 14), rem = (int)(idx & 16383);
        float v = pcW2[l*16384 + rem];
        __nv_bfloat16 h, lo; split_bf(v, h, lo);
        unsigned char* base = g_Bimg + (size_t)l*65536;
        *(__nv_bfloat16*)(base + rem*2)         = h;
        *(__nv_bfloat16*)(base + 32768 + rem*2) = lo;
        return;
    }
    idx -= 81920;
    if (idx < 81920) {
        int l = (int)(idx >> 14), rem = (int)(idx & 16383);
        float v = preW[l*49152 + 32768 + rem];
        __nv_bfloat16 h, lo; split_bf(v, h, lo);
        g_P3I[idx] = h; g_P3I[81920 + idx] = lo;
        return;
    }
    idx -= 81920;
    if (idx < 16384) {
        __nv_bfloat16 h, lo; split_bf(onW1[idx], h, lo);
        g_OnI[idx] = h; g_OnI[16384 + idx] = lo;
        return;
    }
    idx -= 16384;
    if (idx < 16384) {
        __nv_bfloat16 h, lo; split_bf(onW2[idx], h, lo);
        g_OnI[32768 + idx] = h; g_OnI[49152 + idx] = lo;
    }
}

// ---------------- scalar input GEMM -> bf16 hi/lo image output ----------------
__global__ __launch_bounds__(256) void gemm_in_kernel(
    const float* __restrict__ A, int lda,
    const float* __restrict__ W, const float* __restrict__ bias,
    __nv_bfloat16* __restrict__ outH, __nv_bfloat16* __restrict__ outL, int K)
{
    __shared__ float As[16][64];
    __shared__ float Bs[16][128];
    const int t  = threadIdx.x;
    const int m0 = blockIdx.x * 64;
    const int tc = t & 31, tr = t >> 5;
    const int ar = t >> 2;
    const int akq = (t & 3) << 2;

    float acc[8][4];
#pragma unroll
    for (int i = 0; i < 8; i++)
#pragma unroll
        for (int c = 0; c < 4; c++) acc[i][c] = 0.f;

    for (int k0 = 0; k0 < K; k0 += 16) {
        int kg = k0 + akq;
        float4 av = *(const float4*)(A + (size_t)(m0 + ar)*lda + kg);
        As[akq+0][ar] = av.x; As[akq+1][ar] = av.y;
        As[akq+2][ar] = av.z; As[akq+3][ar] = av.w;
#pragma unroll
        for (int i = 0; i < 2; i++) {
            int off = t*8 + i*4;
            int kk = off >> 7, j = off & 127;
            *(float4*)&Bs[kk][j] = *(const float4*)&W[(size_t)(k0+kk)*128 + j];
        }
        __syncthreads();
#pragma unroll
        for (int kk = 0; kk < 16; kk++) {
            float a[8];
            *(float4*)&a[0] = *(const float4*)&As[kk][tr*8];
            *(float4*)&a[4] = *(const float4*)&As[kk][tr*8+4];
            float4 b = *(const float4*)&Bs[kk][tc*4];
#pragma unroll
            for (int i = 0; i < 8; i++) {
                acc[i][0] += a[i]*b.x; acc[i][1] += a[i]*b.y;
                acc[i][2] += a[i]*b.z; acc[i][3] += a[i]*b.w;
            }
        }
        __syncthreads();
    }
    float4 b4 = *(const float4*)&bias[tc*4];
    float bv[4] = {b4.x, b4.y, b4.z, b4.w};
#pragma unroll
    for (int i = 0; i < 8; i++) {
        ushort2 hh[2], ll[2];
#pragma unroll
        for (int c = 0; c < 4; c++) {
            float v = fmaxf(acc[i][c] + bv[c], 0.f);
            __nv_bfloat16 h, lo; split_bf(v, h, lo);
            ((unsigned short*)hh)[c] = __bfloat16_as_ushort(h);
            ((unsigned short*)ll)[c] = __bfloat16_as_ushort(lo);
        }
        size_t o = (size_t)(m0 + tr*8 + i)*128 + tc*4;
        *(uint2*)&outH[o] = *(uint2*)hh;
        *(uint2*)&outL[o] = *(uint2*)ll;
    }
}

// ---------------- tensor GEMM: bf16 hi/lo images, NS-stage cp.async pipeline ----------------
// blockIdx.z selects a "layer": B advances bz per z, fp32 out advances oz per z.
template<bool RELU, int TM, bool IMG, int NS>
__global__ __launch_bounds__(256) void tgemm_bf(
    const __nv_bfloat16* __restrict__ A0H, const __nv_bfloat16* __restrict__ A0L, int lda0,
    const __nv_bfloat16* __restrict__ A1H, const __nv_bfloat16* __restrict__ A1L, int lda1, int Ksplit,
    const __nv_bfloat16* __restrict__ BH, const __nv_bfloat16* __restrict__ BL, int ldb,
    const float* __restrict__ bias,
    float* __restrict__ outF, __nv_bfloat16* __restrict__ outH, __nv_bfloat16* __restrict__ outL,
    int ldo, int K, int bz, int oz)
{
    constexpr int NT = (TM == 128) ? 16 : 8;
    constexpr int ASTG = TM*40*2;
    constexpr int ASTAGE = 2*ASTG;
    constexpr int BIMG = 32*136*2;
    constexpr int BSTAGE = 2*BIMG;
    extern __shared__ __align__(16) char smem[];
    char* sA = smem;
    char* sB = smem + NS*ASTAGE;
    float* sBias = (float*)(smem + NS*ASTAGE + NS*BSTAGE);

    const int z = blockIdx.z;
    BH += (size_t)z * bz;
    BL += (size_t)z * bz;
    if (outF) outF += (size_t)z * oz;

    const int t = threadIdx.x;
    const int w = t >> 5, lid = t & 31;
    const int m0 = blockIdx.x * TM;
    const int n0 = blockIdx.y * 128;
    const int WR = (TM == 128) ? w : (w & 3);
    const int WC = (TM == 128) ? 0 : (w >> 2);

    if (t < 128) sBias[t] = bias ? bias[n0 + t] : 0.f;

    const uint32_t sAb = smem_to_u32(sA);
    const uint32_t sBb = smem_to_u32(sB);

    int arow, acol;
    if (TM == 128) { arow = t >> 1; acol = (t & 1) * 16; }
    else           { arow = t >> 2; acol = (t & 3) * 8; }
    const int bk = t >> 3, bu = (t & 7) * 16;

    auto issue = [&](int kc, int st) {
        int k0 = kc * 32;
        int kg = k0 + acol;
        const __nv_bfloat16 *pH, *pL;
        if (kg < Ksplit) {
            pH = A0H + (size_t)(m0 + arow)*lda0 + kg;
            pL = A0L + (size_t)(m0 + arow)*lda0 + kg;
        } else {
            pH = A1H + (size_t)(m0 + arow)*lda1 + (kg - Ksplit);
            pL = A1L + (size_t)(m0 + arow)*lda1 + (kg - Ksplit);
        }
        uint32_t ad = sAb + st*ASTAGE + (uint32_t)(arow*40 + acol)*2;
        CPA16(ad, pH);
        CPA16(ad + ASTG, pL);
        if (TM == 128) {
            CPA16(ad + 16, pH + 8);
            CPA16(ad + ASTG + 16, pL + 8);
        }
        const __nv_bfloat16* qH = BH + (size_t)(k0 + bk)*ldb + n0 + bu;
        const __nv_bfloat16* qL = BL + (size_t)(k0 + bk)*ldb + n0 + bu;
        uint32_t bd = sBb + st*BSTAGE + (uint32_t)(bk*136 + bu)*2;
        CPA16(bd, qH); CPA16(bd + 16, qH + 8);
        CPA16(bd + BIMG, qL); CPA16(bd + BIMG + 16, qL + 8);
    };

    float acc[NT][4];
#pragma unroll
    for (int nt = 0; nt < NT; nt++)
#pragma unroll
        for (int r = 0; r < 4; r++) acc[nt][r] = 0.f;

    const uint32_t a_off = (uint32_t)((16*WR + (lid & 15))*40 + (lid >> 4)*8) * 2;
    const uint32_t b_off = (uint32_t)(((lid & 7) + ((lid >> 3) & 1)*8)*136 + (lid >> 4)*8 + WC*64) * 2;

    const int nk = K / 32;
#pragma unroll
    for (int s = 0; s < NS-1; s++) {
        if (s < nk) issue(s, s);
        CPC();
    }
    for (int kc = 0; kc < nk; kc++) {
        int st = kc % NS;
        asm volatile("cp.async.wait_group %0;" :: "n"(NS-2) : "memory");
        __syncthreads();
        int kn = kc + NS - 1;
        if (kn < nk) issue(kn, kn % NS);
        CPC();
        uint32_t aH = sAb + st*ASTAGE + a_off;
        uint32_t aL = aH + ASTG;
        uint32_t bHb = sBb + st*BSTAGE + b_off;
        uint32_t bLb = bHb + BIMG;
#pragma unroll
        for (int kh = 0; kh < 2; kh++) {
            uint32_t aH0,aH1,aH2,aH3, aL0,aL1,aL2,aL3;
            LDSM_X4(aH0,aH1,aH2,aH3, aH + kh*32);
            LDSM_X4(aL0,aL1,aL2,aL3, aL + kh*32);
#pragma unroll
            for (int jg = 0; jg < NT/4; jg++) {
                uint32_t bo = kh*4352 + jg*64;
                uint32_t bh0,bh1,bh2,bh3, bh4,bh5,bh6,bh7;
                uint32_t bl0,bl1,bl2,bl3, bl4,bl5,bl6,bl7;
                LDSM_X4_T(bh0,bh1,bh2,bh3, bHb + bo);
                LDSM_X4_T(bh4,bh5,bh6,bh7, bHb + bo + 32);
                LDSM_X4_T(bl0,bl1,bl2,bl3, bLb + bo);
                LDSM_X4_T(bl4,bl5,bl6,bl7, bLb + bo + 32);
                MMA_BF16(acc[4*jg+0], aH0,aH1,aH2,aH3, bh0,bh1);
                MMA_BF16(acc[4*jg+0], aL0,aL1,aL2,aL3, bh0,bh1);
                MMA_BF16(acc[4*jg+0], aH0,aH1,aH2,aH3, bl0,bl1);
                MMA_BF16(acc[4*jg+1], aH0,aH1,aH2,aH3, bh2,bh3);
                MMA_BF16(acc[4*jg+1], aL0,aL1,aL2,aL3, bh2,bh3);
                MMA_BF16(acc[4*jg+1], aH0,aH1,aH2,aH3, bl2,bl3);
                MMA_BF16(acc[4*jg+2], aH0,aH1,aH2,aH3, bh4,bh5);
                MMA_BF16(acc[4*jg+2], aL0,aL1,aL2,aL3, bh4,bh5);
                MMA_BF16(acc[4*jg+2], aH0,aH1,aH2,aH3, bl4,bl5);
                MMA_BF16(acc[4*jg+3], aH0,aH1,aH2,aH3, bh6,bh7);
                MMA_BF16(acc[4*jg+3], aL0,aL1,aL2,aL3, bh6,bh7);
                MMA_BF16(acc[4*jg+3], aH0,aH1,aH2,aH3, bl6,bl7);
            }
        }
    }

    __syncthreads();
    const int r0 = 16*WR + (lid >> 2), r1 = r0 + 8;
    const int cb = 2*(lid & 3);
#pragma unroll
    for (int nt = 0; nt < NT; nt++) {
        int c0 = WC*64 + 8*nt + cb;
        float b0 = sBias[c0], b1 = sBias[c0+1];
        float v0 = acc[nt][0] + b0, v1 = acc[nt][1] + b1;
        float v2 = acc[nt][2] + b0, v3 = acc[nt][3] + b1;
        if (RELU) {
            v0 = fmaxf(v0, 0.f); v1 = fmaxf(v1, 0.f);
            v2 = fmaxf(v2, 0.f); v3 = fmaxf(v3, 0.f);
        }
        if (IMG) {
            __nv_bfloat16 h0,l0,h1,l1,h2,l2,h3,l3;
            split_bf(v0, h0, l0); split_bf(v1, h1, l1);
            split_bf(v2, h2, l2); split_bf(v3, h3, l3);
            *(uint32_t*)&outH[(size_t)(m0 + r0)*ldo + n0 + c0] =
                ((uint32_t)__bfloat16_as_ushort(h1) << 16) | __bfloat16_as_ushort(h0);
            *(uint32_t*)&outL[(size_t)(m0 + r0)*ldo + n0 + c0] =
                ((uint32_t)__bfloat16_as_ushort(l1) << 16) | __bfloat16_as_ushort(l0);
            *(uint32_t*)&outH[(size_t)(m0 + r1)*ldo + n0 + c0] =
                ((uint32_t)__bfloat16_as_ushort(h3) << 16) | __bfloat16_as_ushort(h2);
            *(uint32_t*)&outL[(size_t)(m0 + r1)*ldo + n0 + c0] =
                ((uint32_t)__bfloat16_as_ushort(l3) << 16) | __bfloat16_as_ushort(l2);
        } else {
            *(float2*)&outF[(size_t)(m0 + r0)*ldo + n0 + c0] = make_float2(v0, v1);
            *(float2*)&outF[(size_t)(m0 + r1)*ldo + n0 + c0] = make_float2(v2, v3);
        }
    }
}

// ---------------- fused comp-edge kernel: 2x128-edge subtiles per block, B loaded once ----
#define CS_MS    0                    // 128 x 132 f32 = 67584
#define CS_GS    67584                // 512
#define CS_B2    68096                // 512
#define CS_SEW   68608                // 512
#define CS_AH    69120                // 128 x 136 bf16 = 34816
#define CS_AL    103936
#define CS_BH    138752
#define CS_BL    173568
#define CS_TOTAL 208384

__global__ __launch_bounds__(256, 1) void comp_kernel(
    const int* __restrict__ src,
    int layer,
    const float* __restrict__ b2,
    const float* __restrict__ seW,
    const float* __restrict__ seB)
{
    extern __shared__ __align__(16) char smem[];
    const uint32_t sb = smem_to_u32(smem);
    const int t = threadIdx.x;
    const int w = t >> 5, lid = t & 31;

    float* sM  = (float*)(smem + CS_MS);
    float* sG  = (float*)(smem + CS_GS);
    float* sb2 = (float*)(smem + CS_B2);
    float* ssw = (float*)(smem + CS_SEW);

    if (t < 128) {
        sb2[t] = b2[t];
        ssw[t] = seW[t];
    }

    {   // copy W2 hi/lo images into padded smem [k][136]  (ONCE per block)
        int row = t >> 1, half = t & 1;
        const uint4* srcH = (const uint4*)(g_Bimg + (size_t)layer*65536 + row*256 + half*128);
        const uint4* srcL = (const uint4*)(g_Bimg + (size_t)layer*65536 + 32768 + row*256 + half*128);
        uint4* dstH = (uint4*)(smem + CS_BH + row*272 + half*128);
        uint4* dstL = (uint4*)(smem + CS_BL + row*272 + half*128);
#pragma unroll
        for (int i = 0; i < 8; i++) { dstH[i] = srcH[i]; dstL[i] = srcL[i]; }
    }

    const uint32_t a_addr = sb + CS_AH + (uint32_t)((16*w + (lid & 15)) * 136 + (lid >> 4) * 8) * 2;
    const uint32_t b_addr = sb + CS_BH + (uint32_t)(((lid & 7) + ((lid >> 3) & 1) * 8) * 136 + (lid >> 4) * 8) * 2;

    for (int sub = 0; sub < 2; sub++) {
        const int e0 = blockIdx.x * 256 + sub * 128;

        {   // build A tile: gather + add + relu, bf16 hi/lo
            int row = t >> 1, half = t & 1;
            int s = src[e0 + row];
            int node = (e0 >> 4) + (row >> 4);
            const float* x1 = g_X + (size_t)s*512 + half*64;
            const float* x2 = g_X + (size_t)node*512 + 128 + half*64;
            uint32_t* ah = (uint32_t*)(smem + CS_AH + row*272 + half*128);
            uint32_t* al = (uint32_t*)(smem + CS_AL + row*272 + half*128);
#pragma unroll
            for (int i = 0; i < 64; i += 4) {
                float4 a = *(const float4*)(x1 + i);
                float4 b = *(const float4*)(x2 + i);
                float v0 = fmaxf(a.x + b.x, 0.f), v1 = fmaxf(a.y + b.y, 0.f);
                float v2 = fmaxf(a.z + b.z, 0.f), v3 = fmaxf(a.w + b.w, 0.f);
                __nv_bfloat16 h0,l0,h1,l1,h2,l2,h3,l3;
                split_bf(v0,h0,l0); split_bf(v1,h1,l1);
                split_bf(v2,h2,l2); split_bf(v3,h3,l3);
                ah[i/2]   = ((uint32_t)__bfloat16_as_ushort(h1) << 16) | __bfloat16_as_ushort(h0);
                ah[i/2+1] = ((uint32_t)__bfloat16_as_ushort(h3) << 16) | __bfloat16_as_ushort(h2);
                al[i/2]   = ((uint32_t)__bfloat16_as_ushort(l1) << 16) | __bfloat16_as_ushort(l0);
                al[i/2+1] = ((uint32_t)__bfloat16_as_ushort(l3) << 16) | __bfloat16_as_ushort(l2);
            }
        }
        __syncthreads();

        float acc[16][4];
#pragma unroll
        for (int nt = 0; nt < 16; nt++)
#pragma unroll
            for (int r = 0; r < 4; r++) acc[nt][r] = 0.f;

        for (int ks = 0; ks < 8; ks++) {
            uint32_t aH0,aH1,aH2,aH3, aL0,aL1,aL2,aL3;
            uint32_t aoff = a_addr + ks*32;
            LDSM_X4(aH0,aH1,aH2,aH3, aoff);
            LDSM_X4(aL0,aL1,aL2,aL3, aoff + (CS_AL - CS_AH));
#pragma unroll
            for (int jg = 0; jg < 4; jg++) {
                uint32_t bofs = b_addr + ks*4352 + jg*64;
                uint32_t bh0,bh1,bh2,bh3, bh4,bh5,bh6,bh7;
                uint32_t bl0,bl1,bl2,bl3, bl4,bl5,bl6,bl7;
                LDSM_X4_T(bh0,bh1,bh2,bh3, bofs);
                LDSM_X4_T(bh4,bh5,bh6,bh7, bofs + 32);
                LDSM_X4_T(bl0,bl1,bl2,bl3, bofs + (CS_BL - CS_BH));
                LDSM_X4_T(bl4,bl5,bl6,bl7, bofs + (CS_BL - CS_BH) + 32);
                MMA_BF16(acc[4*jg+0], aH0,aH1,aH2,aH3, bh0,bh1);
                MMA_BF16(acc[4*jg+0], aL0,aL1,aL2,aL3, bh0,bh1);
                MMA_BF16(acc[4*jg+0], aH0,aH1,aH2,aH3, bl0,bl1);
                MMA_BF16(acc[4*jg+1], aH0,aH1,aH2,aH3, bh2,bh3);
                MMA_BF16(acc[4*jg+1], aL0,aL1,aL2,aL3, bh2,bh3);
                MMA_BF16(acc[4*jg+1], aH0,aH1,aH2,aH3, bl2,bl3);
                MMA_BF16(acc[4*jg+2], aH0,aH1,aH2,aH3, bh4,bh5);
                MMA_BF16(acc[4*jg+2], aL0,aL1,aL2,aL3, bh4,bh5);
                MMA_BF16(acc[4*jg+2], aH0,aH1,aH2,aH3, bl4,bl5);
                MMA_BF16(acc[4*jg+3], aH0,aH1,aH2,aH3, bh6,bh7);
                MMA_BF16(acc[4*jg+3], aL0,aL1,aL2,aL3, bh6,bh7);
                MMA_BF16(acc[4*jg+3], aH0,aH1,aH2,aH3, bl6,bl7);
            }
        }

        {   // epilogue: bias + gate partials + stage to sM
            int r0 = 16*w + (lid >> 2);
            int r1 = r0 + 8;
            int cb = 2*(lid & 3);
            float p0 = 0.f, p1 = 0.f;
#pragma unroll
            for (int nt = 0; nt < 16; nt++) {
                int c0 = 8*nt + cb;
                float bb0 = sb2[c0], bb1 = sb2[c0+1];
                float w0 = ssw[c0], w1 = ssw[c0+1];
                float m0 = acc[nt][0] + bb0, m1 = acc[nt][1] + bb1;
                float m2 = acc[nt][2] + bb0, m3 = acc[nt][3] + bb1;
                p0 += m0*w0 + m1*w1;
                p1 += m2*w0 + m3*w1;
                sM[r0*132 + c0]     = m0;
                sM[r0*132 + c0 + 1] = m1;
                sM[r1*132 + c0]     = m2;
                sM[r1*132 + c0 + 1] = m3;
            }
            p0 += __shfl_xor_sync(0xffffffffu, p0, 1);
            p0 += __shfl_xor_sync(0xffffffffu, p0, 2);
            p1 += __shfl_xor_sync(0xffffffffu, p1, 1);
            p1 += __shfl_xor_sync(0xffffffffu, p1, 2);
            if ((lid & 3) == 0) {
                float sbv = seB[0];
                sG[r0] = 1.f / (1.f + expf(-(p0 + sbv)));
                sG[r1] = 1.f / (1.f + expf(-(p1 + sbv)));
            }
        }
        __syncthreads();

        // PNA stats: 8 nodes x 128 cols, write bf16 hi/lo agg images
#pragma unroll
        for (int q = 0; q < 4; q++) {
            int item = q*256 + t;
            int n8 = item >> 7, col = item & 127;
            float s = 0.f, sq = 0.f, mx = -INFINITY, mn = INFINITY;
#pragma unroll
            for (int i = 0; i < 16; i++) {
                int row = n8*16 + i;
                float v = sM[row*132 + col] * sG[row];
                s += v; sq += v*v; mx = fmaxf(mx, v); mn = fminf(mn, v);
            }
            int node = (e0 >> 4) + n8;
            float mean = s * 0.0625f;
            float sd = sqrtf(fmaxf(sq*0.0625f - mean*mean, 0.f) + 1e-5f);
            size_t base = (size_t)node*1024 + 512 + col;
            float vs[4] = {mean, mx, mn, sd};
#pragma unroll
            for (int z = 0; z < 4; z++) {
                __nv_bfloat16 h, lo; split_bf(vs[z], h, lo);
                g_aggI[base + z*128]        = h;
                g_aggI[AGGN + base + z*128] = lo;
            }
        }
        __syncthreads();   // before next subtile overwrites A / sM / sG
    }
}

// ---------------- bond-edge PNA (standalone, reads per-layer C5 slice) ----------------
__global__ __launch_bounds__(256) void bond_kernel(const int* __restrict__ src,
                                                   const float* __restrict__ Cl) {
    int idx = blockIdx.x*256 + threadIdx.x;   // NN*128 total
    int n = idx >> 7, j = idx & 127;
    float base = g_X[(size_t)n*512 + 384 + j];
    float s=0.f, q=0.f, mx=-INFINITY, mn=INFINITY;
#pragma unroll
    for (int e = 0; e < 4; e++) {
        int ei = n*4 + e;
        int sv = src[ei];
        float v = g_X[(size_t)sv*512 + 256 + j] + base + Cl[(size_t)ei*128 + j];
        s += v; q += v*v; mx = fmaxf(mx, v); mn = fminf(mn, v);
    }
    float mean = s*0.25f;
    float sd = sqrtf(fmaxf(q*0.25f - mean*mean, 0.f) + 1e-5f);
    size_t ob = (size_t)n*1024 + j;
    float vs[4] = {mean, mx, mn, sd};
#pragma unroll
    for (int z = 0; z < 4; z++) {
        __nv_bfloat16 h, lo; split_bf(vs[z], h, lo);
        g_aggI[ob + z*128]        = h;
        g_aggI[AGGN + ob + z*128] = lo;
    }
}

// ---------------- readout ----------------
__global__ __launch_bounds__(128) void readout_kernel(
    const float* __restrict__ h3,
    const float* __restrict__ W1, const float* __restrict__ b1,
    const float* __restrict__ W2, const float* __restrict__ b2,
    float* __restrict__ out)
{
    __shared__ float r[384];
    __shared__ float tb[128];
    int g = blockIdx.x, j = threadIdx.x;
    const float* p = h3 + (size_t)g*100*128 + j;
    float s = 0.f, mx = -INFINITY;
    for (int i = 0; i < 100; i++) {
        float v = p[i*128];
        s += v; mx = fmaxf(mx, v);
    }
    r[j] = s; r[128+j] = s/100.f; r[256+j] = mx;
    __syncthreads();
    float a = b1[j];
    for (int k = 0; k < 384; k++) a += r[k]*W1[k*128 + j];
    tb[j] = fmaxf(a, 0.f);
    __syncthreads();
    if (j < 32) {
        float o = b2[j];
        for (int k = 0; k < 128; k++) o += tb[k]*W2[k*32 + j];
        out[g*32 + j] = o;
    }
}

// ---------------- launcher ----------------
extern "C" void kernel_launch(void* const* d_in, const int* in_sizes, int n_in,
                              void* d_out, int out_size) {
    const float* node_feat = (const float*)d_in[0];
    const float* edge_feat = (const float*)d_in[1];
    const int*   bond_src  = (const int*)d_in[2];
    const int*   comp_src  = (const int*)d_in[4];
    const float* in_W   = (const float*)d_in[7];
    const float* in_b   = (const float*)d_in[8];
    const float* ein_W  = (const float*)d_in[9];
    const float* ein_b  = (const float*)d_in[10];
    const float* pre_W  = (const float*)d_in[11];
    const float* pre_b  = (const float*)d_in[12];
    const float* pc_W1  = (const float*)d_in[13];
    const float* pc_b1  = (const float*)d_in[14];
    const float* pc_W2  = (const float*)d_in[15];
    const float* pc_b2  = (const float*)d_in[16];
    const float* se_W   = (const float*)d_in[17];
    const float* se_b   = (const float*)d_in[18];
    const float* post_W = (const float*)d_in[19];
    const float* post_b = (const float*)d_in[20];
    const float* outn_W1 = (const float*)d_in[21];
    const float* outn_b1 = (const float*)d_in[22];
    const float* outn_W2 = (const float*)d_in[23];
    const float* outn_b2 = (const float*)d_in[24];
    const float* ro_W1 = (const float*)d_in[25];
    const float* ro_b1 = (const float*)d_in[26];
    const float* ro_W2 = (const float*)d_in[27];
    const float* ro_b2 = (const float*)d_in[28];

    float *hA, *X, *C5, *bx;
    __nv_bfloat16 *WxI, *P3I, *WeI, *OnI, *hIA, *hIB, *efI, *aggI, *t1I;
    cudaGetSymbolAddress((void**)&hA, g_hA);
    cudaGetSymbolAddress((void**)&X,  g_X);
    cudaGetSymbolAddress((void**)&C5, g_C5);
    cudaGetSymbolAddress((void**)&bx, g_bx);
    cudaGetSymbolAddress((void**)&WxI, g_WxI);
    cudaGetSymbolAddress((void**)&P3I, g_P3I);
    cudaGetSymbolAddress((void**)&WeI, g_WeI);
    cudaGetSymbolAddress((void**)&OnI, g_OnI);
    cudaGetSymbolAddress((void**)&hIA, g_hImgA);
    cudaGetSymbolAddress((void**)&hIB, g_hImgB);
    cudaGetSymbolAddress((void**)&efI, g_efI);
    cudaGetSymbolAddress((void**)&aggI, g_aggI);
    cudaGetSymbolAddress((void**)&t1I, g_t1I);

    const int SM128 = 2*(2*128*40*2) + 2*(2*32*136*2) + 512;   // 76288
    const int SM64  = 3*(2*64*40*2)  + 3*(2*32*136*2) + 512;   // 83456
    cudaFuncSetAttribute(comp_kernel, cudaFuncAttributeMaxDynamicSharedMemorySize, CS_TOTAL);
    cudaFuncSetAttribute(tgemm_bf<false,128,false,2>, cudaFuncAttributeMaxDynamicSharedMemorySize, SM128);
    cudaFuncSetAttribute(tgemm_bf<false,64,true,3>,  cudaFuncAttributeMaxDynamicSharedMemorySize, SM64);
    cudaFuncSetAttribute(tgemm_bf<true,64,true,3>,   cudaFuncAttributeMaxDynamicSharedMemorySize, SM64);
    cudaFuncSetAttribute(tgemm_bf<false,64,false,3>, cudaFuncAttributeMaxDynamicSharedMemorySize, SM64);

    pack_all_kernel<<<4928, 256>>>(pc_W1, pre_W, pc_b1, pre_b, post_W, pc_W2, outn_W1, outn_W2);

    // input transforms -> bf16 hi/lo images
    gemm_in_kernel<<<NN/64, 256>>>(node_feat, 64, in_W, in_b, hIA, hIA + NN*128, 64);
    gemm_in_kernel<<<EB/64, 256>>>(edge_feat, 16, ein_W, ein_b, efI, efI + EB*128, 16);

    // C for ALL 5 layers in one launch (ef constant across layers)
    tgemm_bf<false,128,false,2><<<dim3(EB/128, 1, 5), 256, SM128>>>(
        efI, efI + EB*128, 128, efI, efI + EB*128, 128, 128,
        P3I, P3I + 5*16384, 128,
        nullptr, C5, nullptr, nullptr, 128, 128, 16384, EB*128);

    __nv_bfloat16* cur = hIA;   // hi at cur, lo at cur + NN*128
    __nv_bfloat16* nxt = hIB;
    for (int l = 0; l < 5; l++) {
        // X = h @ [W1a | W1b | P1 | P2] + [0 | b1 | 0 | preb]  (fp32 out)
        tgemm_bf<false,128,false,2><<<dim3(NN/128, 4, 1), 256, SM128>>>(
            cur, cur + NN*128, 128, cur, cur + NN*128, 128, 128,
            WxI + l*65536, WxI + 5*65536 + l*65536, 512,
            bx + l*512, X, nullptr, nullptr, 512, 128, 0, 0);
        bond_kernel<<<NN*128/256, 256>>>(bond_src, C5 + (size_t)l*EB*128);
        comp_kernel<<<EC/256, 256, CS_TOTAL>>>(comp_src, l, pc_b2 + l*128,
                                               se_W + l*128, se_b + l);
        // h_next = [h | agg] @ W_eff + post_b  (image out, residual+scalers folded)
        tgemm_bf<false,64,true,3><<<dim3(NN/64, 1, 1), 256, SM64>>>(
            cur, cur + NN*128, 128, aggI, aggI + AGGN, 1024, 128,
            WeI + l*147456, WeI + 5*147456 + l*147456, 128,
            post_b + l*128, nullptr, nxt, nxt + NN*128, 128, 1152, 0, 0);
        __nv_bfloat16* tmp = cur; cur = nxt; nxt = tmp;
    }

    // node-wise output MLP
    tgemm_bf<true,64,true,3><<<dim3(NN/64, 1, 1), 256, SM64>>>(
        cur, cur + NN*128, 128, cur, cur + NN*128, 128, 128,
        OnI, OnI + 16384, 128,
        outn_b1, nullptr, t1I, t1I + NN*128, 128, 128, 0, 0);
    tgemm_bf<false,64,false,3><<<dim3(NN/64, 1, 1), 256, SM64>>>(
        t1I, t1I + NN*128, 128, t1I, t1I + NN*128, 128, 128,
        OnI + 32768, OnI + 49152, 128,
        outn_b2, hA, nullptr, nullptr, 128, 128, 0, 0);
    // readout
    readout_kernel<<<GG, 128>>>(hA, ro_W1, ro_b1, ro_W2, ro_b2, (float*)d_out);
}